// round 13
// baseline (speedup 1.0000x reference)
#include <cuda_runtime.h>
#include <cuda_bf16.h>
#include <math.h>
#include <stdint.h>

#define N 4096
#define D 512
#define MARGIN 0.3f
#define BIG 1000000.0f
#define NT 32                       // 4096/128 tile grid
#define NBLK (NT * (NT + 1) / 2)    // 528 upper-triangular tiles

// ---------------- scratch (no allocs allowed) ----------------
__device__ float g_dist[(size_t)N * N];            // 64 MB: squared distances (d2)
__device__ uint32_t g_h8[(size_t)N * D / 4];       // int8 hi digit (packed)
__device__ uint32_t g_l8[(size_t)N * D / 4];       // int8 lo digit (packed)
__device__ float g_sq[N];
__device__ int   g_hp_bits[N];                     // hp^2 bits (atomicMax, >0)
__device__ int   g_fb_bits[N];                     // fb^2 bits
__device__ int   g_smin_bits[N];                   // min d2 over {d2 > hp2} (atomicMin)
__device__ int   g_done;

// ---------------- PTX helpers ----------------
__device__ __forceinline__ uint32_t smem_u32(const void* p) {
    return (uint32_t)__cvta_generic_to_shared(p);
}
__device__ __forceinline__ void cp16(uint32_t dst, const void* src) {
    asm volatile("cp.async.cg.shared.global [%0], [%1], 16;" :: "r"(dst), "l"(src));
}
#define LDSM4(r0, r1, r2, r3, addr)                                          \
    asm volatile("ldmatrix.sync.aligned.m8n8.x4.shared.b16 {%0,%1,%2,%3}, [%4];" \
                 : "=r"(r0), "=r"(r1), "=r"(r2), "=r"(r3) : "r"(addr))
#define MMA_S8(acc, a, b)                                                    \
    asm volatile("mma.sync.aligned.m16n8k32.row.col.s32.s8.s8.s32 "          \
                 "{%0,%1,%2,%3}, {%4,%5,%6,%7}, {%8,%9}, {%0,%1,%2,%3};"     \
                 : "+r"((acc)[0]), "+r"((acc)[1]), "+r"((acc)[2]), "+r"((acc)[3]) \
                 : "r"((a)[0]), "r"((a)[1]), "r"((a)[2]), "r"((a)[3]),       \
                   "r"((b)[0]), "r"((b)[1]))

// ---------------- 1: prep — warp-per-row int8 2-digit split + sq-norms + init ----------------
__global__ __launch_bounds__(256) void prep_kernel(const float* __restrict__ E) {
    const int w = threadIdx.x >> 5, lane = threadIdx.x & 31;
    const int row = blockIdx.x * 8 + w;
    const float* __restrict__ src = E + (size_t)row * D;
    float s = 0.0f;
#pragma unroll
    for (int q = 0; q < 4; q++) {
        const int col = (lane + 32 * q) * 4;
        const float4 v = *(const float4*)&src[col];
        const float f[4] = {v.x, v.y, v.z, v.w};
        uint32_t hp = 0, lp = 0;
#pragma unroll
        for (int u = 0; u < 4; u++) {
            s += f[u] * f[u];
            int h = __float2int_rn(f[u] * 16.0f);
            h = max(-127, min(127, h));
            const int l = __float2int_rn(fmaf(f[u], 2048.0f, (float)(-128 * h)));
            hp |= ((uint32_t)(uint8_t)(int8_t)h) << (u * 8);
            lp |= ((uint32_t)(uint8_t)(int8_t)l) << (u * 8);
        }
        g_h8[((size_t)row * D + col) / 4] = hp;
        g_l8[((size_t)row * D + col) / 4] = lp;
    }
    for (int o = 16; o > 0; o >>= 1) s += __shfl_down_sync(0xFFFFFFFF, s, o);
    if (lane == 0) {
        g_sq[row] = s;
        g_hp_bits[row] = 0;
        g_fb_bits[row] = 0;
        g_smin_bits[row] = 0x7F7FFFFF;      // FLT_MAX bits
    }
    if (blockIdx.x == 0 && threadIdx.x == 0) g_done = 0;
}

// ---------------- 2: symmetric int8 split-GEMM (IMMA) -> d2(+mirror) + hp2/fb2 ----------------
#define BM 128
#define BN 128
#define KS 16                    // 512 / 32 bytes per stage
#define ROWI 48                  // 32 B data + 16 B pad (conflict-free ldmatrix)
#define TI8 (128 * ROWI)         // 6144 per tile
#define SM_LJ 0
#define SM_LI 512
#define SM_SQJ 1024
#define SM_SQI 1536
#define SM_OPS 2048
#define STG_STRIDE 132
#define GEMM_SMEM (SM_OPS + 128 * STG_STRIDE * 4)   // 69632 (stg region >= 8*TI8=49152)

#define S1 0.00390625f           // 16384 / 2048^2 = 2^-8
#define S2 3.0517578125e-5f      // 128   / 2048^2 = 2^-15

__global__ __launch_bounds__(256) void gemm_s8(const int* __restrict__ labels) {
    extern __shared__ char smem[];
    const int tid = threadIdx.x, lane = tid & 31, wid = tid >> 5;
    const int wm = wid >> 2, wn = wid & 3;          // 2 x 4 warp grid
    const int gid = lane >> 2, tig = lane & 3;

    // map linear block id -> upper-triangular tile (bi <= bj)
    int b = blockIdx.x, bi = 0;
    while (b >= NT - bi) { b -= NT - bi; bi++; }
    const int bj = bi + b;
    const int i0 = bi * BM, j0 = bj * BN;
    const bool diag = (bi == bj);

    const uint32_t sb = smem_u32(smem);
    int*   lj  = (int*)(smem + SM_LJ);
    int*   li  = (int*)(smem + SM_LI);
    float* sqj = (float*)(smem + SM_SQJ);
    float* sqi = (float*)(smem + SM_SQI);
    if (tid < 128) { lj[tid] = labels[j0 + tid]; sqj[tid] = g_sq[j0 + tid]; }
    else { const int t2 = tid - 128; li[t2] = labels[i0 + t2]; sqi[t2] = g_sq[i0 + t2]; }

    int hh[4][4][4], mm[4][4][4];
#pragma unroll
    for (int mt = 0; mt < 4; mt++)
#pragma unroll
        for (int nt = 0; nt < 4; nt++)
#pragma unroll
            for (int k = 0; k < 4; k++) { hh[mt][nt][k] = 0; mm[mt][nt][k] = 0; }

    // one stage = 4 tiles x 128 rows x 2 chunks(16B) = 1024 cp.async; 256 thr x 4 iters
    auto load_stage = [&](int st, int k0) {
        const uint32_t base = sb + SM_OPS + ((st & 1) ? 4 * TI8 : 0);
        const int r = tid & 127, c = tid >> 7;
#pragma unroll
        for (int tile = 0; tile < 4; tile++) {
            const int grow = ((tile >= 2) ? j0 : i0) + r;
            const char* src = (const char*)((tile & 1) ? g_l8 : g_h8) +
                              (size_t)grow * D + k0 + c * 16;
            cp16(base + tile * TI8 + r * ROWI + c * 16, src);
        }
    };

    load_stage(0, 0);
    asm volatile("cp.async.commit_group;" ::: "memory");

    // ldmatrix lane offsets
    const uint32_t a_off = (lane < 16) ? (uint32_t)(lane * ROWI)
                                       : (uint32_t)((lane - 16) * ROWI + 16);
    const uint32_t b_off = (uint32_t)((((lane & 7) + ((lane >> 4) << 3)) * ROWI) +
                                      ((lane & 8) ? 16 : 0));

    for (int t = 0; t < KS; t++) {
        if (t + 1 < KS) {
            load_stage(t + 1, (t + 1) * 32);
            asm volatile("cp.async.commit_group;" ::: "memory");
            asm volatile("cp.async.wait_group 1;" ::: "memory");
        } else {
            asm volatile("cp.async.wait_group 0;" ::: "memory");
        }
        __syncthreads();

        const uint32_t base = sb + SM_OPS + ((t & 1) ? 4 * TI8 : 0);
        const uint32_t Ah = base, Al = base + TI8;
        const uint32_t Bh = base + 2 * TI8, Bl = base + 3 * TI8;

        uint32_t ah[4][4], al_[4][4], bh[4][2], bl[4][2];
#pragma unroll
        for (int mt = 0; mt < 4; mt++) {
            const uint32_t off = (wm * 64 + mt * 16) * ROWI;
            LDSM4(ah[mt][0], ah[mt][1], ah[mt][2], ah[mt][3], Ah + off + a_off);
            LDSM4(al_[mt][0], al_[mt][1], al_[mt][2], al_[mt][3], Al + off + a_off);
        }
#pragma unroll
        for (int q = 0; q < 2; q++) {
            const uint32_t off = (wn * 32 + q * 16) * ROWI + b_off;
            uint32_t r0, r1, r2, r3;
            LDSM4(r0, r1, r2, r3, Bh + off);
            bh[q * 2][0] = r0; bh[q * 2][1] = r1;
            bh[q * 2 + 1][0] = r2; bh[q * 2 + 1][1] = r3;
            LDSM4(r0, r1, r2, r3, Bl + off);
            bl[q * 2][0] = r0; bl[q * 2][1] = r1;
            bl[q * 2 + 1][0] = r2; bl[q * 2 + 1][1] = r3;
        }
#pragma unroll
        for (int mt = 0; mt < 4; mt++)
#pragma unroll
            for (int nt = 0; nt < 4; nt++) {
                MMA_S8(hh[mt][nt], ah[mt], bh[nt]);    // hi*hi   (scale 2^-8)
                MMA_S8(mm[mt][nt], ah[mt], bl[nt]);    // hi*lo   (scale 2^-15)
                MMA_S8(mm[mt][nt], al_[mt], bh[nt]);   // lo*hi   (scale 2^-15)
            }
        __syncthreads();
    }

    // ---- stage fp32 dots to smem (exact: |acc| < 2^24, power-of-2 scales) ----
    float* stg = (float*)(smem + SM_OPS);
#pragma unroll
    for (int mt = 0; mt < 4; mt++)
#pragma unroll
        for (int nt = 0; nt < 4; nt++) {
            const int r0 = wm * 64 + mt * 16 + gid;
            const int c0 = wn * 32 + nt * 8 + tig * 2;
            float d[4];
#pragma unroll
            for (int k = 0; k < 4; k++)
                d[k] = fmaf((float)hh[mt][nt][k], S1, (float)mm[mt][nt][k] * S2);
            *(float2*)&stg[r0 * STG_STRIDE + c0] = make_float2(d[0], d[1]);
            *(float2*)&stg[(r0 + 8) * STG_STRIDE + c0] = make_float2(d[2], d[3]);
        }
    __syncthreads();

    // ---- row pass: d2, write [i,j] block, hp2/fb2 for i-rows ----
#pragma unroll 1
    for (int rr = 0; rr < 16; rr++) {
        const int row = wid * 16 + rr;
        const float4 v = *(const float4*)&stg[row * STG_STRIDE + lane * 4];
        const float sqiv = sqi[row];
        const int liv = li[row];
        float hp = 0.0f, fb = 0.0f;
        float o[4];
#pragma unroll
        for (int u = 0; u < 4; u++) {
            const int jc = lane * 4 + u;
            const float d2 = fmaxf(fmaf(-2.0f, (&v.x)[u], sqiv + sqj[jc]), 1e-12f);
            o[u] = d2;
            if (lj[jc] == liv) hp = fmaxf(hp, d2);
            else               fb = fmaxf(fb, d2);
        }
        *(float4*)&g_dist[(size_t)(i0 + row) * N + j0 + lane * 4] =
            make_float4(o[0], o[1], o[2], o[3]);
#pragma unroll
        for (int off = 16; off > 0; off >>= 1) {
            hp = fmaxf(hp, __shfl_down_sync(0xFFFFFFFF, hp, off));
            fb = fmaxf(fb, __shfl_down_sync(0xFFFFFFFF, fb, off));
        }
        if (lane == 0) {
            atomicMax(&g_hp_bits[i0 + row], __float_as_int(hp));
            atomicMax(&g_fb_bits[i0 + row], __float_as_int(fb));
        }
    }

    // ---- mirror pass (off-diagonal): recompute d2 from dots, write [j,i], hp/fb ----
    if (!diag) {
#pragma unroll 1
        for (int rr = 0; rr < 16; rr++) {
            const int jrow = wid * 16 + rr;       // row within j-tile
            const int ljv = lj[jrow];
            const float sqjv = sqj[jrow];
            float hp = 0.0f, fb = 0.0f;
#pragma unroll
            for (int u = 0; u < 4; u++) {
                const int il = lane + 32 * u;     // column within i-tile
                const float dot = stg[il * STG_STRIDE + jrow];
                const float d2 = fmaxf(fmaf(-2.0f, dot, sqi[il] + sqjv), 1e-12f);
                if (li[il] == ljv) hp = fmaxf(hp, d2);
                else               fb = fmaxf(fb, d2);
                g_dist[(size_t)(j0 + jrow) * N + i0 + il] = d2;
            }
#pragma unroll
            for (int off = 16; off > 0; off >>= 1) {
                hp = fmaxf(hp, __shfl_down_sync(0xFFFFFFFF, hp, off));
                fb = fmaxf(fb, __shfl_down_sync(0xFFFFFFFF, fb, off));
            }
            if (lane == 0) {
                atomicMax(&g_hp_bits[j0 + jrow], __float_as_int(hp));
                atomicMax(&g_fb_bits[j0 + jrow], __float_as_int(fb));
            }
        }
    }
}

// ---------------- 3: lean scan, full MLP — min over {d2 > hp2} ----------------
#define RPB 4     // rows per block, 1024 blocks
__global__ __launch_bounds__(256) void rowstats4(float* __restrict__ out) {
    const int t = threadIdx.x, lane = t & 31;

#pragma unroll 1
    for (int r = 0; r < RPB; r++) {
        const int i = blockIdx.x * RPB + r;
        const float hp2v = __int_as_float(g_hp_bits[i]);
        const float4* __restrict__ row4 = (const float4*)&g_dist[(size_t)i * N];

        const float4 v0 = row4[t];
        const float4 v1 = row4[t + 256];
        const float4 v2 = row4[t + 512];
        const float4 v3 = row4[t + 768];

        float m0 = 3.4e38f, m1 = 3.4e38f, m2 = 3.4e38f, m3 = 3.4e38f;
        if (v0.x > hp2v) m0 = v0.x;
        if (v0.y > hp2v) m1 = v0.y;
        if (v0.z > hp2v) m2 = v0.z;
        if (v0.w > hp2v) m3 = v0.w;
        if (v1.x > hp2v) m0 = fminf(m0, v1.x);
        if (v1.y > hp2v) m1 = fminf(m1, v1.y);
        if (v1.z > hp2v) m2 = fminf(m2, v1.z);
        if (v1.w > hp2v) m3 = fminf(m3, v1.w);
        if (v2.x > hp2v) m0 = fminf(m0, v2.x);
        if (v2.y > hp2v) m1 = fminf(m1, v2.y);
        if (v2.z > hp2v) m2 = fminf(m2, v2.z);
        if (v2.w > hp2v) m3 = fminf(m3, v2.w);
        if (v3.x > hp2v) m0 = fminf(m0, v3.x);
        if (v3.y > hp2v) m1 = fminf(m1, v3.y);
        if (v3.z > hp2v) m2 = fminf(m2, v3.z);
        if (v3.w > hp2v) m3 = fminf(m3, v3.w);

        float mins = fminf(fminf(m0, m1), fminf(m2, m3));
#pragma unroll
        for (int off = 16; off > 0; off >>= 1)
            mins = fminf(mins, __shfl_down_sync(0xFFFFFFFF, mins, off));
        if (lane == 0)
            atomicMin(&g_smin_bits[i], __float_as_int(mins));
    }

    // ---- done counter; last block computes the loss ----
    __threadfence();
    __syncthreads();
    __shared__ int s_last;
    if (t == 0) s_last = (atomicAdd(&g_done, 1) == (N / RPB) - 1) ? 1 : 0;
    __syncthreads();
    if (!s_last) return;
    __threadfence();

    __shared__ double rs[256], rf[256];
    __shared__ int rcs[256], rcf[256], rany[256];
    double ss = 0.0, sf = 0.0;
    int cs = 0, cf = 0, any = 0;
    for (int i = t; i < N; i += 256) {
        const float hp2 = __int_as_float(g_hp_bits[i]);
        const float hpv = sqrtf(hp2);
        const float hib = hpv + MARGIN;
        const float m2 = __int_as_float(g_smin_bits[i]);
        const bool has = (m2 < hib * hib);          // min above hp2 inside window?
        any |= has ? 1 : 0;
        const float hns = has ? sqrtf(m2) : BIG;
        const float fbv = sqrtf(__int_as_float(g_fb_bits[i]));
        const float trs = fmaxf(hpv - hns + MARGIN, 0.0f);
        const float trf = fmaxf(hpv - fbv + MARGIN, 0.0f);
        ss += (double)trs; cs += (trs > 0.0f) ? 1 : 0;
        sf += (double)trf; cf += (trf > 0.0f) ? 1 : 0;
    }
    rs[t] = ss; rf[t] = sf; rcs[t] = cs; rcf[t] = cf; rany[t] = any;
    __syncthreads();
    for (int s = 128; s > 0; s >>= 1) {
        if (t < s) {
            rs[t] += rs[t + s]; rf[t] += rf[t + s];
            rcs[t] += rcs[t + s]; rcf[t] += rcf[t + s];
            rany[t] |= rany[t + s];
        }
        __syncthreads();
    }
    if (t == 0) {
        const bool semi = rany[0] != 0;
        const double s = semi ? rs[0] : rf[0];
        const int c = semi ? rcs[0] : rcf[0];
        out[0] = (float)(s / (double)(c > 0 ? c : 1));
    }
}

// ---------------- launcher ----------------
extern "C" void kernel_launch(void* const* d_in, const int* in_sizes, int n_in,
                              void* d_out, int out_size) {
    const float* E = (const float*)d_in[0];
    const int* labels = (const int*)d_in[1];
    float* out = (float*)d_out;

    cudaFuncSetAttribute(gemm_s8, cudaFuncAttributeMaxDynamicSharedMemorySize, GEMM_SMEM);

    prep_kernel<<<N / 8, 256>>>(E);
    gemm_s8<<<NBLK, 256, GEMM_SMEM>>>(labels);
    rowstats4<<<N / RPB, 256>>>(out);
}

// round 14
// speedup vs baseline: 1.8920x; 1.8920x over previous
#include <cuda_runtime.h>
#include <cuda_bf16.h>
#include <math.h>
#include <stdint.h>

#define N 4096
#define D 512
#define MARGIN 0.3f
#define BIG 1000000.0f
#define NT 32                       // 4096/128 tile grid
#define NBLK (NT * (NT + 1) / 2)    // 528 upper-triangular tiles

// ---------------- scratch (no allocs allowed) ----------------
__device__ float g_dist[(size_t)N * N];            // 64 MB: squared distances (d2)
__device__ __nv_bfloat16 g_hi[(size_t)N * D];      // bf16 hi split
__device__ __nv_bfloat16 g_lo[(size_t)N * D];      // bf16 lo split
__device__ float g_sq[N];
__device__ int   g_hp_bits[N];                     // hp^2 bits (atomicMax, >0)
__device__ int   g_fb_bits[N];                     // fb^2 bits
__device__ int   g_smin_bits[N];                   // min d2 over {d2 > hp2} (atomicMin)
__device__ int   g_done;

// ---------------- PTX helpers ----------------
__device__ __forceinline__ uint32_t smem_u32(const void* p) {
    return (uint32_t)__cvta_generic_to_shared(p);
}
__device__ __forceinline__ void cp16(uint32_t dst, const void* src) {
    asm volatile("cp.async.cg.shared.global [%0], [%1], 16;" :: "r"(dst), "l"(src));
}
#define LDSM4(r0, r1, r2, r3, addr)                                          \
    asm volatile("ldmatrix.sync.aligned.m8n8.x4.shared.b16 {%0,%1,%2,%3}, [%4];" \
                 : "=r"(r0), "=r"(r1), "=r"(r2), "=r"(r3) : "r"(addr))
#define MMA_BF16(acc, a, b)                                                  \
    asm volatile("mma.sync.aligned.m16n8k16.row.col.f32.bf16.bf16.f32 "      \
                 "{%0,%1,%2,%3}, {%4,%5,%6,%7}, {%8,%9}, {%0,%1,%2,%3};"     \
                 : "+f"((acc)[0]), "+f"((acc)[1]), "+f"((acc)[2]), "+f"((acc)[3]) \
                 : "r"((a)[0]), "r"((a)[1]), "r"((a)[2]), "r"((a)[3]),       \
                   "r"((b)[0]), "r"((b)[1]))

// ---------------- 1: prep — warp-per-row bf16 split + sq-norms + init ----------------
__global__ __launch_bounds__(256) void prep_kernel(const float* __restrict__ E) {
    const int w = threadIdx.x >> 5, lane = threadIdx.x & 31;
    const int row = blockIdx.x * 8 + w;
    const float* __restrict__ src = E + (size_t)row * D;
    float s = 0.0f;
#pragma unroll
    for (int q = 0; q < 4; q++) {
        const int col = (lane + 32 * q) * 4;
        const float4 v = *(const float4*)&src[col];
        const float f[4] = {v.x, v.y, v.z, v.w};
        uint32_t hp[2], lp[2];
#pragma unroll
        for (int p = 0; p < 2; p++) {
            const float a = f[2 * p], b = f[2 * p + 1];
            s += a * a + b * b;
            const __nv_bfloat16 ha = __float2bfloat16(a);
            const __nv_bfloat16 hb = __float2bfloat16(b);
            const __nv_bfloat16 la = __float2bfloat16(a - __bfloat162float(ha));
            const __nv_bfloat16 lb = __float2bfloat16(b - __bfloat162float(hb));
            hp[p] = ((uint32_t)__bfloat16_as_ushort(hb) << 16) | __bfloat16_as_ushort(ha);
            lp[p] = ((uint32_t)__bfloat16_as_ushort(lb) << 16) | __bfloat16_as_ushort(la);
        }
        *(uint2*)&g_hi[(size_t)row * D + col] = make_uint2(hp[0], hp[1]);
        *(uint2*)&g_lo[(size_t)row * D + col] = make_uint2(lp[0], lp[1]);
    }
    for (int o = 16; o > 0; o >>= 1) s += __shfl_down_sync(0xFFFFFFFF, s, o);
    if (lane == 0) {
        g_sq[row] = s;
        g_hp_bits[row] = 0;
        g_fb_bits[row] = 0;
        g_smin_bits[row] = 0x7F7FFFFF;      // FLT_MAX bits
    }
    if (blockIdx.x == 0 && threadIdx.x == 0) g_done = 0;
}

// ---------------- 2: symmetric bf16 split-GEMM, 128 thr, 64x64 warp tile ----------------
#define BM 128
#define BN 128
#define KS 16                    // 512 / 32
#define ROWB 80                  // 32 bf16 = 64B + 16B pad
#define TILEB (128 * ROWB)       // 10240 per tile
#define SM_LJ 0
#define SM_LI 512
#define SM_SQJ 1024
#define SM_SQI 1536
#define SM_OPS 2048
#define GEMM_SMEM (SM_OPS + 8 * TILEB)     // 83968
#define STG_STRIDE 132

__global__ __launch_bounds__(128) void gemm_bf16(const int* __restrict__ labels) {
    extern __shared__ char smem[];
    const int tid = threadIdx.x, lane = tid & 31, wid = tid >> 5;
    const int wm = wid >> 1, wn = wid & 1;          // 2 x 2 warp grid, 64x64 tiles
    const int gid = lane >> 2, tig = lane & 3;

    // map linear block id -> upper-triangular tile (bi <= bj)
    int b = blockIdx.x, bi = 0;
    while (b >= NT - bi) { b -= NT - bi; bi++; }
    const int bj = bi + b;
    const int i0 = bi * BM, j0 = bj * BN;
    const bool diag = (bi == bj);

    const uint32_t sb = smem_u32(smem);
    int*   lj  = (int*)(smem + SM_LJ);
    int*   li  = (int*)(smem + SM_LI);
    float* sqj = (float*)(smem + SM_SQJ);
    float* sqi = (float*)(smem + SM_SQI);
    if (tid < 128) {
        lj[tid] = labels[j0 + tid]; sqj[tid] = g_sq[j0 + tid];
        li[tid] = labels[i0 + tid]; sqi[tid] = g_sq[i0 + tid];
    }

    float acc[4][8][4];
#pragma unroll
    for (int mt = 0; mt < 4; mt++)
#pragma unroll
        for (int nt = 0; nt < 8; nt++)
#pragma unroll
            for (int k = 0; k < 4; k++) acc[mt][nt][k] = 0.0f;

    // one stage = 4 tiles x 512 chunks of 16B = 2048 cp.async; 128 thr x 16 iters
    auto load_stage = [&](int st, int k0e) {
        const uint32_t base = sb + SM_OPS + ((st & 1) ? 4 * TILEB : 0);
#pragma unroll
        for (int i = 0; i < 16; i++) {
            const int idx = tid + i * 128;
            const int tile = idx >> 9;          // 0:Ah 1:Al 2:Bh 3:Bl
            const int id = idx & 511;
            const int r = id >> 2, c = id & 3;
            const int grow = ((tile >= 2) ? j0 : i0) + r;
            const __nv_bfloat16* src =
                ((tile & 1) ? g_lo : g_hi) + (size_t)grow * D + k0e + c * 8;
            cp16(base + tile * TILEB + r * ROWB + c * 16, src);
        }
    };

    load_stage(0, 0);
    asm volatile("cp.async.commit_group;" ::: "memory");

    for (int t = 0; t < KS; t++) {
        if (t + 1 < KS) {
            load_stage(t + 1, (t + 1) * 32);
            asm volatile("cp.async.commit_group;" ::: "memory");
            asm volatile("cp.async.wait_group 1;" ::: "memory");
        } else {
            asm volatile("cp.async.wait_group 0;" ::: "memory");
        }
        __syncthreads();

        const uint32_t base = sb + SM_OPS + ((t & 1) ? 4 * TILEB : 0);
        const uint32_t Ah = base, Al = base + TILEB;
        const uint32_t Bh = base + 2 * TILEB, Bl = base + 3 * TILEB;
        const uint32_t arow = (wm * 64 + (lane & 15)) * ROWB + (lane >> 4) * 16;
        const uint32_t brow = (wn * 64 + (lane & 15)) * ROWB + (lane >> 4) * 16;

#pragma unroll
        for (int kk = 0; kk < 2; kk++) {
            uint32_t ah[4][4], al_[4][4], bh[8][2], bl[8][2];
#pragma unroll
            for (int mt = 0; mt < 4; mt++) {
                const uint32_t off = arow + mt * 16 * ROWB + kk * 32;
                LDSM4(ah[mt][0], ah[mt][1], ah[mt][2], ah[mt][3], Ah + off);
                LDSM4(al_[mt][0], al_[mt][1], al_[mt][2], al_[mt][3], Al + off);
            }
#pragma unroll
            for (int p = 0; p < 4; p++) {
                const uint32_t off = brow + p * 16 * ROWB + kk * 32;
                uint32_t r0, r1, r2, r3;
                LDSM4(r0, r1, r2, r3, Bh + off);
                bh[p * 2][0] = r0; bh[p * 2][1] = r2;
                bh[p * 2 + 1][0] = r1; bh[p * 2 + 1][1] = r3;
                LDSM4(r0, r1, r2, r3, Bl + off);
                bl[p * 2][0] = r0; bl[p * 2][1] = r2;
                bl[p * 2 + 1][0] = r1; bl[p * 2 + 1][1] = r3;
            }
#pragma unroll
            for (int mt = 0; mt < 4; mt++)
#pragma unroll
                for (int nt = 0; nt < 8; nt++) {
                    MMA_BF16(acc[mt][nt], ah[mt], bh[nt]);   // hi*hi
                    MMA_BF16(acc[mt][nt], ah[mt], bl[nt]);   // hi*lo
                    MMA_BF16(acc[mt][nt], al_[mt], bh[nt]);  // lo*hi
                }
        }
        __syncthreads();
    }

    // ---- stage fp32 dots to smem (read-only afterwards) ----
    float* stg = (float*)(smem + SM_OPS);
#pragma unroll
    for (int mt = 0; mt < 4; mt++)
#pragma unroll
        for (int nt = 0; nt < 8; nt++) {
            const int r0 = wm * 64 + mt * 16 + gid;
            const int c0 = wn * 64 + nt * 8 + tig * 2;
            *(float2*)&stg[r0 * STG_STRIDE + c0] = make_float2(acc[mt][nt][0], acc[mt][nt][1]);
            *(float2*)&stg[(r0 + 8) * STG_STRIDE + c0] = make_float2(acc[mt][nt][2], acc[mt][nt][3]);
        }
    __syncthreads();

    // ---- row pass: d2, write [i,j] block, hp2/fb2 for i-rows (32 rows/warp) ----
#pragma unroll 1
    for (int rr = 0; rr < 32; rr++) {
        const int row = wid * 32 + rr;
        const float4 v = *(const float4*)&stg[row * STG_STRIDE + lane * 4];
        const float sqiv = sqi[row];
        const int liv = li[row];
        float hp = 0.0f, fb = 0.0f;
        float o[4];
#pragma unroll
        for (int u = 0; u < 4; u++) {
            const int jc = lane * 4 + u;
            const float d2 = fmaxf(fmaf(-2.0f, (&v.x)[u], sqiv + sqj[jc]), 1e-12f);
            o[u] = d2;
            if (lj[jc] == liv) hp = fmaxf(hp, d2);
            else               fb = fmaxf(fb, d2);
        }
        *(float4*)&g_dist[(size_t)(i0 + row) * N + j0 + lane * 4] =
            make_float4(o[0], o[1], o[2], o[3]);
#pragma unroll
        for (int off = 16; off > 0; off >>= 1) {
            hp = fmaxf(hp, __shfl_down_sync(0xFFFFFFFF, hp, off));
            fb = fmaxf(fb, __shfl_down_sync(0xFFFFFFFF, fb, off));
        }
        if (lane == 0) {
            atomicMax(&g_hp_bits[i0 + row], __float_as_int(hp));
            atomicMax(&g_fb_bits[i0 + row], __float_as_int(fb));
        }
    }

    // ---- mirror pass (off-diagonal): recompute d2 from dots, write [j,i], hp/fb ----
    if (!diag) {
#pragma unroll 1
        for (int rr = 0; rr < 32; rr++) {
            const int jrow = wid * 32 + rr;       // row within j-tile
            const int ljv = lj[jrow];
            const float sqjv = sqj[jrow];
            float hp = 0.0f, fb = 0.0f;
#pragma unroll
            for (int u = 0; u < 4; u++) {
                const int il = lane + 32 * u;     // column within i-tile
                const float dot = stg[il * STG_STRIDE + jrow];
                const float d2 = fmaxf(fmaf(-2.0f, dot, sqi[il] + sqjv), 1e-12f);
                if (li[il] == ljv) hp = fmaxf(hp, d2);
                else               fb = fmaxf(fb, d2);
                g_dist[(size_t)(j0 + jrow) * N + i0 + il] = d2;
            }
#pragma unroll
            for (int off = 16; off > 0; off >>= 1) {
                hp = fmaxf(hp, __shfl_down_sync(0xFFFFFFFF, hp, off));
                fb = fmaxf(fb, __shfl_down_sync(0xFFFFFFFF, fb, off));
            }
            if (lane == 0) {
                atomicMax(&g_hp_bits[j0 + jrow], __float_as_int(hp));
                atomicMax(&g_fb_bits[j0 + jrow], __float_as_int(fb));
            }
        }
    }
}

// ---------------- 3: lean scan, full MLP — min over {d2 > hp2} ----------------
#define RPB 4     // rows per block, 1024 blocks
__global__ __launch_bounds__(256) void rowstats4(float* __restrict__ out) {
    const int t = threadIdx.x, lane = t & 31;

#pragma unroll 1
    for (int r = 0; r < RPB; r++) {
        const int i = blockIdx.x * RPB + r;
        const float hp2v = __int_as_float(g_hp_bits[i]);
        const float4* __restrict__ row4 = (const float4*)&g_dist[(size_t)i * N];

        const float4 v0 = row4[t];
        const float4 v1 = row4[t + 256];
        const float4 v2 = row4[t + 512];
        const float4 v3 = row4[t + 768];

        float m0 = 3.4e38f, m1 = 3.4e38f, m2 = 3.4e38f, m3 = 3.4e38f;
        if (v0.x > hp2v) m0 = v0.x;
        if (v0.y > hp2v) m1 = v0.y;
        if (v0.z > hp2v) m2 = v0.z;
        if (v0.w > hp2v) m3 = v0.w;
        if (v1.x > hp2v) m0 = fminf(m0, v1.x);
        if (v1.y > hp2v) m1 = fminf(m1, v1.y);
        if (v1.z > hp2v) m2 = fminf(m2, v1.z);
        if (v1.w > hp2v) m3 = fminf(m3, v1.w);
        if (v2.x > hp2v) m0 = fminf(m0, v2.x);
        if (v2.y > hp2v) m1 = fminf(m1, v2.y);
        if (v2.z > hp2v) m2 = fminf(m2, v2.z);
        if (v2.w > hp2v) m3 = fminf(m3, v2.w);
        if (v3.x > hp2v) m0 = fminf(m0, v3.x);
        if (v3.y > hp2v) m1 = fminf(m1, v3.y);
        if (v3.z > hp2v) m2 = fminf(m2, v3.z);
        if (v3.w > hp2v) m3 = fminf(m3, v3.w);

        float mins = fminf(fminf(m0, m1), fminf(m2, m3));
#pragma unroll
        for (int off = 16; off > 0; off >>= 1)
            mins = fminf(mins, __shfl_down_sync(0xFFFFFFFF, mins, off));
        if (lane == 0)
            atomicMin(&g_smin_bits[i], __float_as_int(mins));
    }

    // ---- done counter; last block computes the loss ----
    __threadfence();
    __syncthreads();
    __shared__ int s_last;
    if (t == 0) s_last = (atomicAdd(&g_done, 1) == (N / RPB) - 1) ? 1 : 0;
    __syncthreads();
    if (!s_last) return;
    __threadfence();

    __shared__ double rs[256], rf[256];
    __shared__ int rcs[256], rcf[256], rany[256];
    double ss = 0.0, sf = 0.0;
    int cs = 0, cf = 0, any = 0;
    for (int i = t; i < N; i += 256) {
        const float hp2 = __int_as_float(g_hp_bits[i]);
        const float hpv = sqrtf(hp2);
        const float hib = hpv + MARGIN;
        const float m2 = __int_as_float(g_smin_bits[i]);
        const bool has = (m2 < hib * hib);          // min above hp2 inside window?
        any |= has ? 1 : 0;
        const float hns = has ? sqrtf(m2) : BIG;
        const float fbv = sqrtf(__int_as_float(g_fb_bits[i]));
        const float trs = fmaxf(hpv - hns + MARGIN, 0.0f);
        const float trf = fmaxf(hpv - fbv + MARGIN, 0.0f);
        ss += (double)trs; cs += (trs > 0.0f) ? 1 : 0;
        sf += (double)trf; cf += (trf > 0.0f) ? 1 : 0;
    }
    rs[t] = ss; rf[t] = sf; rcs[t] = cs; rcf[t] = cf; rany[t] = any;
    __syncthreads();
    for (int s = 128; s > 0; s >>= 1) {
        if (t < s) {
            rs[t] += rs[t + s]; rf[t] += rf[t + s];
            rcs[t] += rcs[t + s]; rcf[t] += rcf[t + s];
            rany[t] |= rany[t + s];
        }
        __syncthreads();
    }
    if (t == 0) {
        const bool semi = rany[0] != 0;
        const double s = semi ? rs[0] : rf[0];
        const int c = semi ? rcs[0] : rcf[0];
        out[0] = (float)(s / (double)(c > 0 ? c : 1));
    }
}

// ---------------- launcher ----------------
extern "C" void kernel_launch(void* const* d_in, const int* in_sizes, int n_in,
                              void* d_out, int out_size) {
    const float* E = (const float*)d_in[0];
    const int* labels = (const int*)d_in[1];
    float* out = (float*)d_out;

    cudaFuncSetAttribute(gemm_bf16, cudaFuncAttributeMaxDynamicSharedMemorySize, GEMM_SMEM);

    prep_kernel<<<N / 8, 256>>>(E);
    gemm_bf16<<<NBLK, 128, GEMM_SMEM>>>(labels);
    rowstats4<<<N / RPB, 256>>>(out);
}